// round 5
// baseline (speedup 1.0000x reference)
#include <cuda_runtime.h>
#include <math.h>

#define NN    8192
#define INC   512
#define SLOT  192
#define PMASK 0x7FFFFFFF
#define TPB   256

// ---------------- scratch (device globals) -----------------------------------
__device__ float g_h1[NN * 64];
__device__ float g_als1[NN * 8];
__device__ float g_ald1[NN * 8];
__device__ float g_out1[NN * 64];
__device__ float g_h2[NN * 64];
__device__ float g_als2[NN];
__device__ float g_ald2[NN];
__device__ float g_x2[NN * 64];
__device__ float g_s2[NN * 64];
__device__ float g_tmp2[NN * 64];
__device__ float g_pool[2 * 4096];     // [0]=out_adj accum, [4096]=x_pool accum
__device__ int   g_cnt[NN];
__device__ __align__(16) int g_slot[NN * SLOT];
__device__ unsigned g_barrier[2];      // [0]=arrive, [1]=release (memset to 0 per launch)

// ---------------- helpers ----------------------------------------------------
__device__ __forceinline__ float warpSum(float v) {
    #pragma unroll
    for (int o = 16; o > 0; o >>= 1) v += __shfl_xor_sync(0xffffffffu, v, o);
    return v;
}
__device__ __forceinline__ float warpMax(float v) {
    #pragma unroll
    for (int o = 16; o > 0; o >>= 1) v = fmaxf(v, __shfl_xor_sync(0xffffffffu, v, o));
    return v;
}
__device__ __forceinline__ float lrelu(float v) { return v > 0.f ? v : 0.2f * v; }

__device__ __forceinline__ void fma2(unsigned long long& d, unsigned long long a, unsigned long long b) {
    asm("fma.rn.f32x2 %0, %1, %2, %0;" : "+l"(d) : "l"(a), "l"(b));
}
__device__ __forceinline__ unsigned long long splat2(float a) {
    unsigned long long r;
    asm("mov.b64 %0, {%1, %1};" : "=l"(r) : "f"(a));
    return r;
}

// grid-wide barrier (all blocks resident by construction)
__device__ __forceinline__ void gridBar(int G) {
    __syncthreads();
    if (threadIdx.x == 0) {
        __threadfence();
        unsigned arr = atomicAdd(&g_barrier[0], 1u) + 1u;
        unsigned gen = (arr + (unsigned)G - 1u) / (unsigned)G;
        if (arr == gen * (unsigned)G) {
            atomicAdd(&g_barrier[1], 1u);         // release this generation
        } else {
            while (atomicAdd(&g_barrier[1], 0u) < gen) { __nanosleep(64); }
        }
    }
    __syncthreads();
}

// ---------------- sgemm tiles (64x64 out, shared-union) -----------------------
__device__ void sgemm1_tile(const float* __restrict__ A, const float* __restrict__ B,
                            const float* __restrict__ asrc, const float* __restrict__ adst,
                            float* __restrict__ C, int row0, float* sh) {
    float (*As)[68] = (float(*)[68])sh;              // 2176 floats
    float (*Bs)[64] = (float(*)[64])(sh + 2176);     // 2048 floats
    float (*Cs)[66] = (float(*)[66])sh;              // 4224 floats (aliases As+Bs)
    int tid = threadIdx.x;
    int ty = tid >> 4, tx = tid & 15;
    unsigned long long acc[4][2] = {};
    for (int k0 = 0; k0 < INC; k0 += 32) {
        #pragma unroll
        for (int i = tid; i < 64 * 32; i += TPB) {
            int m = i >> 5, k = i & 31;
            As[k][m] = A[(row0 + m) * INC + k0 + k];
        }
        #pragma unroll
        for (int i = tid; i < 32 * 64; i += TPB) {
            int k = i >> 6, n = i & 63;
            Bs[k][n] = B[(k0 + k) * 64 + n];
        }
        __syncthreads();
        #pragma unroll
        for (int k = 0; k < 32; k++) {
            float4 a4 = *(const float4*)&As[k][ty * 4];
            const unsigned long long* bp = (const unsigned long long*)&Bs[k][tx * 4];
            unsigned long long b01 = bp[0], b23 = bp[1];
            unsigned long long s0 = splat2(a4.x), s1 = splat2(a4.y),
                               s2 = splat2(a4.z), s3 = splat2(a4.w);
            fma2(acc[0][0], s0, b01); fma2(acc[0][1], s0, b23);
            fma2(acc[1][0], s1, b01); fma2(acc[1][1], s1, b23);
            fma2(acc[2][0], s2, b01); fma2(acc[2][1], s2, b23);
            fma2(acc[3][0], s3, b01); fma2(acc[3][1], s3, b23);
        }
        __syncthreads();
    }
    #pragma unroll
    for (int i = 0; i < 4; i++) {
        unsigned long long* cp = (unsigned long long*)&C[(row0 + ty * 4 + i) * 64 + tx * 4];
        cp[0] = acc[i][0]; cp[1] = acc[i][1];
        unsigned long long* sp = (unsigned long long*)&Cs[ty * 4 + i][tx * 4];
        sp[0] = acc[i][0]; sp[1] = acc[i][1];
    }
    __syncthreads();
    #pragma unroll
    for (int idx = tid; idx < 512; idx += TPB) {
        int n = idx >> 3, h = idx & 7;
        const float* hp = &Cs[n][h * 8];
        float s = 0.f, d = 0.f;
        #pragma unroll
        for (int c = 0; c < 8; c++) {
            s += hp[c] * __ldg(asrc + h * 8 + c);
            d += hp[c] * __ldg(adst + h * 8 + c);
        }
        g_als1[(row0 + n) * 8 + h] = s;
        g_ald1[(row0 + n) * 8 + h] = d;
    }
    __syncthreads();   // protect Cs before next tile overwrites As/Bs
}

__device__ void sgemm2_tile(const float* __restrict__ A, const float* __restrict__ B,
                            const float* __restrict__ asrc, const float* __restrict__ adst,
                            float* __restrict__ C, int row0, float* sh) {
    float (*As)[68] = (float(*)[68])sh;
    float (*Bs)[64] = (float(*)[64])(sh + 2176);
    float (*Cs)[66] = (float(*)[66])sh;
    int tid = threadIdx.x;
    int ty = tid >> 4, tx = tid & 15;
    unsigned long long acc[4][2] = {};
    for (int k0 = 0; k0 < 64; k0 += 32) {
        #pragma unroll
        for (int i = tid; i < 64 * 32; i += TPB) {
            int m = i >> 5, k = i & 31;
            As[k][m] = A[(row0 + m) * 64 + k0 + k];
        }
        #pragma unroll
        for (int i = tid; i < 32 * 64; i += TPB) {
            int k = i >> 6, n = i & 63;
            Bs[k][n] = B[(k0 + k) * 64 + n];
        }
        __syncthreads();
        #pragma unroll
        for (int k = 0; k < 32; k++) {
            float4 a4 = *(const float4*)&As[k][ty * 4];
            const unsigned long long* bp = (const unsigned long long*)&Bs[k][tx * 4];
            unsigned long long b01 = bp[0], b23 = bp[1];
            unsigned long long s0 = splat2(a4.x), s1 = splat2(a4.y),
                               s2 = splat2(a4.z), s3 = splat2(a4.w);
            fma2(acc[0][0], s0, b01); fma2(acc[0][1], s0, b23);
            fma2(acc[1][0], s1, b01); fma2(acc[1][1], s1, b23);
            fma2(acc[2][0], s2, b01); fma2(acc[2][1], s2, b23);
            fma2(acc[3][0], s3, b01); fma2(acc[3][1], s3, b23);
        }
        __syncthreads();
    }
    #pragma unroll
    for (int i = 0; i < 4; i++) {
        unsigned long long* cp = (unsigned long long*)&C[(row0 + ty * 4 + i) * 64 + tx * 4];
        cp[0] = acc[i][0]; cp[1] = acc[i][1];
        unsigned long long* sp = (unsigned long long*)&Cs[ty * 4 + i][tx * 4];
        sp[0] = acc[i][0]; sp[1] = acc[i][1];
    }
    __syncthreads();
    {   // att2: 4 threads per node
        int n = tid >> 2, q = tid & 3;
        const float* hp = &Cs[n][q * 16];
        float s = 0.f, d = 0.f;
        #pragma unroll
        for (int c = 0; c < 16; c++) {
            float hv = hp[c];
            s += hv * __ldg(asrc + q * 16 + c);
            d += hv * __ldg(adst + q * 16 + c);
        }
        s += __shfl_xor_sync(0xffffffffu, s, 1);
        s += __shfl_xor_sync(0xffffffffu, s, 2);
        d += __shfl_xor_sync(0xffffffffu, d, 1);
        d += __shfl_xor_sync(0xffffffffu, d, 2);
        if (q == 0) { g_als2[row0 + n] = s; g_ald2[row0 + n] = d; }
    }
    __syncthreads();
}

// ---------------- the fused persistent kernel ---------------------------------
__global__ void __launch_bounds__(TPB, 4)
fused_kernel(const float* __restrict__ x, const int* __restrict__ ei, int E,
             const float* __restrict__ W1, const float* __restrict__ asrc1,
             const float* __restrict__ adst1, const float* __restrict__ b1,
             const float* __restrict__ W2, const float* __restrict__ asrc2,
             const float* __restrict__ adst2, const float* __restrict__ b2,
             float* __restrict__ out, int G) {
    __shared__ __align__(16) float sh[4224];   // 16896B union
    const int bid = blockIdx.x;
    const int tid = threadIdx.x;
    const int lane = tid & 31;
    const int gw = bid * (TPB / 32) + (tid >> 5);
    const int nwarp = G * (TPB / 32);
    const int q4 = (E >> 2) + NN;

    // ---- P0: zero counters + pool accumulators ----
    for (int i = bid * TPB + tid; i < NN; i += G * TPB) g_cnt[i] = 0;
    for (int i = bid * TPB + tid; i < 2 * 4096; i += G * TPB) g_pool[i] = 0.f;
    gridBar(G);

    // ---- P1: sgemm1+att1 (blocks <128) || bucket build (rest) ----
    for (int t = bid; t < 128; t += G)
        sgemm1_tile(x, W1, asrc1, adst1, g_h1, t * 64, sh);
    {
        int gp = (G >= 160) ? (G - 128) : G;
        int bs = G - gp;
        if (bid >= bs) {
            for (int i = (bid - bs) * TPB + tid; i < q4; i += gp * TPB) {
                if (i < (E >> 2)) {
                    int4 s4 = __ldg((const int4*)ei + i);
                    int4 d4 = __ldg((const int4*)(ei + E) + i);
                    int p0 = atomicAdd(&g_cnt[d4.x], 1);
                    int p1 = atomicAdd(&g_cnt[d4.y], 1);
                    int p2 = atomicAdd(&g_cnt[d4.z], 1);
                    int p3 = atomicAdd(&g_cnt[d4.w], 1);
                    if (p0 < SLOT) g_slot[d4.x * SLOT + p0] = s4.x;
                    if (p1 < SLOT) g_slot[d4.y * SLOT + p1] = s4.y;
                    if (p2 < SLOT) g_slot[d4.z * SLOT + p2] = s4.z;
                    if (p3 < SLOT) g_slot[d4.w * SLOT + p3] = s4.w;
                } else {
                    int n = i - (E >> 2);
                    int p = atomicAdd(&g_cnt[n], 1);
                    if (p < SLOT) g_slot[n * SLOT + p] = n | 0x80000000;
                }
            }
        }
    }
    gridBar(G);

    // ---- P2: gather1 (warp per node) ----
    for (int node = gw; node < NN; node += nwarp) {
        int c0 = lane * 2;
        int h = lane >> 2;
        int cnt = min(g_cnt[node], SLOT);
        int base = node * SLOT;
        float ald = __ldg(g_ald1 + node * 8 + h);
        float a0c = 0.f, a1c = 0.f, den = 0.f;
        int e = 0;
        for (; e + 4 <= cnt; e += 4) {
            int4 pv = *(const int4*)(g_slot + base + e);
            int p0 = pv.x & PMASK, p1 = pv.y & PMASK, p2 = pv.z & PMASK, p3 = pv.w & PMASK;
            float s0 = __ldg(g_als1 + p0 * 8 + h);
            float s1 = __ldg(g_als1 + p1 * 8 + h);
            float s2 = __ldg(g_als1 + p2 * 8 + h);
            float s3 = __ldg(g_als1 + p3 * 8 + h);
            float2 h0 = *(const float2*)(g_h1 + p0 * 64 + c0);
            float2 h1 = *(const float2*)(g_h1 + p1 * 64 + c0);
            float2 h2 = *(const float2*)(g_h1 + p2 * 64 + c0);
            float2 h3 = *(const float2*)(g_h1 + p3 * 64 + c0);
            float x0 = __expf(lrelu(s0 + ald));
            float x1 = __expf(lrelu(s1 + ald));
            float x2 = __expf(lrelu(s2 + ald));
            float x3 = __expf(lrelu(s3 + ald));
            den += (x0 + x1) + (x2 + x3);
            a0c += x0 * h0.x + x1 * h1.x + x2 * h2.x + x3 * h3.x;
            a1c += x0 * h0.y + x1 * h1.y + x2 * h2.y + x3 * h3.y;
        }
        for (; e < cnt; e++) {
            int p = g_slot[base + e] & PMASK;
            float xv = __expf(lrelu(__ldg(g_als1 + p * 8 + h) + ald));
            float2 hv = *(const float2*)(g_h1 + p * 64 + c0);
            den += xv;
            a0c += xv * hv.x;
            a1c += xv * hv.y;
        }
        den += 1e-16f;
        float v0 = a0c / den + __ldg(b1 + c0);
        float v1 = a1c / den + __ldg(b1 + c0 + 1);
        float2 o;
        o.x = v0 > 0.f ? v0 : (__expf(v0) - 1.f);
        o.y = v1 > 0.f ? v1 : (__expf(v1) - 1.f);
        *(float2*)(g_out1 + node * 64 + c0) = o;
    }
    gridBar(G);

    // ---- P3: sgemm2 + att2 ----
    for (int t = bid; t < 128; t += G)
        sgemm2_tile(g_out1, W2, asrc2, adst2, g_h2, t * 64, sh);
    gridBar(G);

    // ---- P4: gather2 + bias + double softmax ----
    for (int node = gw; node < NN; node += nwarp) {
        int c0 = lane * 2;
        int cnt = min(g_cnt[node], SLOT);
        int base = node * SLOT;
        float ald = __ldg(g_ald2 + node);
        float a0c = 0.f, a1c = 0.f, den = 0.f;
        int e = 0;
        for (; e + 4 <= cnt; e += 4) {
            int4 pv = *(const int4*)(g_slot + base + e);
            int p0 = pv.x & PMASK, p1 = pv.y & PMASK, p2 = pv.z & PMASK, p3 = pv.w & PMASK;
            float s0 = __ldg(g_als2 + p0);
            float s1 = __ldg(g_als2 + p1);
            float s2 = __ldg(g_als2 + p2);
            float s3 = __ldg(g_als2 + p3);
            float2 h0 = *(const float2*)(g_h2 + p0 * 64 + c0);
            float2 h1 = *(const float2*)(g_h2 + p1 * 64 + c0);
            float2 h2v = *(const float2*)(g_h2 + p2 * 64 + c0);
            float2 h3 = *(const float2*)(g_h2 + p3 * 64 + c0);
            float x0 = __expf(lrelu(s0 + ald));
            float x1 = __expf(lrelu(s1 + ald));
            float x2 = __expf(lrelu(s2 + ald));
            float x3 = __expf(lrelu(s3 + ald));
            den += (x0 + x1) + (x2 + x3);
            a0c += x0 * h0.x + x1 * h1.x + x2 * h2v.x + x3 * h3.x;
            a1c += x0 * h0.y + x1 * h1.y + x2 * h2v.y + x3 * h3.y;
        }
        for (; e < cnt; e++) {
            int p = g_slot[base + e] & PMASK;
            float xv = __expf(lrelu(__ldg(g_als2 + p) + ald));
            float2 hv = *(const float2*)(g_h2 + p * 64 + c0);
            den += xv;
            a0c += xv * hv.x;
            a1c += xv * hv.y;
        }
        den += 1e-16f;
        float v0 = a0c / den + __ldg(b2 + c0);
        float v1 = a1c / den + __ldg(b2 + c0 + 1);
        *(float2*)(g_x2 + node * 64 + c0) = make_float2(v0, v1);
        float m = warpMax(fmaxf(v0, v1));
        float e0 = __expf(v0 - m), e1 = __expf(v1 - m);
        float sum = warpSum(e0 + e1);
        float s0 = e0 / sum, s1 = e1 / sum;
        *(float2*)(out + 2 * 4096 + node * 64 + c0) = make_float2(s0, s1);
        float m2 = warpMax(fmaxf(s0, s1));
        float f0 = __expf(s0 - m2), f1 = __expf(s1 - m2);
        float sum2 = warpSum(f0 + f1);
        *(float2*)(g_s2 + node * 64 + c0) = make_float2(f0 / sum2, f1 / sum2);
    }
    gridBar(G);

    // ---- P5: adjacency gather tmp2 = A @ s2 ----
    for (int node = gw; node < NN; node += nwarp) {
        int c0 = lane * 2;
        int cnt = min(g_cnt[node], SLOT);
        int base = node * SLOT;
        float a0c = 0.f, a1c = 0.f;
        int e = 0;
        for (; e + 4 <= cnt; e += 4) {
            int4 pv = *(const int4*)(g_slot + base + e);
            int q0 = pv.x & PMASK, q1 = pv.y & PMASK, q2 = pv.z & PMASK, q3 = pv.w & PMASK;
            float2 s0 = *(const float2*)(g_s2 + q0 * 64 + c0);
            float2 s1 = *(const float2*)(g_s2 + q1 * 64 + c0);
            float2 s2v = *(const float2*)(g_s2 + q2 * 64 + c0);
            float2 s3 = *(const float2*)(g_s2 + q3 * 64 + c0);
            if (pv.x >= 0) { a0c += s0.x; a1c += s0.y; }
            if (pv.y >= 0) { a0c += s1.x; a1c += s1.y; }
            if (pv.z >= 0) { a0c += s2v.x; a1c += s2v.y; }
            if (pv.w >= 0) { a0c += s3.x; a1c += s3.y; }
        }
        for (; e < cnt; e++) {
            int p = g_slot[base + e];
            if (p < 0) continue;
            float2 sv = *(const float2*)(g_s2 + p * 64 + c0);
            a0c += sv.x;
            a1c += sv.y;
        }
        *(float2*)(g_tmp2 + node * 64 + c0) = make_float2(a0c, a1c);
    }
    gridBar(G);

    // ---- P6: pool reduction (64x64 outputs) ----
    for (int chunk = bid; chunk < 128; chunk += G) {
        int i = tid >> 2;
        int jb = (tid & 3) * 16;
        int base = chunk * 64;
        float accA[16] = {}, accX[16] = {};
        for (int n = 0; n < 64; n++) {
            int node = base + n;
            float ti = __ldg(g_tmp2 + node * 64 + i);
            float si = __ldg(g_s2 + node * 64 + i);
            const float4* s4 = (const float4*)(g_s2 + node * 64 + jb);
            const float4* x4 = (const float4*)(g_x2 + node * 64 + jb);
            #pragma unroll
            for (int q = 0; q < 4; q++) {
                float4 sv = __ldg(s4 + q), xv = __ldg(x4 + q);
                accA[q * 4 + 0] += ti * sv.x; accA[q * 4 + 1] += ti * sv.y;
                accA[q * 4 + 2] += ti * sv.z; accA[q * 4 + 3] += ti * sv.w;
                accX[q * 4 + 0] += si * xv.x; accX[q * 4 + 1] += si * xv.y;
                accX[q * 4 + 2] += si * xv.z; accX[q * 4 + 3] += si * xv.w;
            }
        }
        #pragma unroll
        for (int u = 0; u < 16; u++) {
            atomicAdd(&g_pool[i * 64 + jb + u], accA[u]);
            atomicAdd(&g_pool[4096 + i * 64 + jb + u], accX[u]);
        }
    }
    gridBar(G);

    // ---- P7: finalize (block 0) ----
    if (bid == 0) {
        float* sd = sh;
        int i = tid;
        if (i < 64) {
            float rs = 0.f;
            for (int j = 0; j < 64; j++) {
                float v = (j == i) ? 0.f : g_pool[i * 64 + j];
                rs += v;
            }
            sd[i] = sqrtf(rs) + 1e-15f;
        }
        __syncthreads();
        if (i < 64) {
            for (int j = 0; j < 64; j++) {
                float v = (j == i) ? 0.f : g_pool[i * 64 + j];
                out[4096 + i * 64 + j] = v / sd[j] / sd[i];
                out[i * 64 + j] = g_pool[4096 + i * 64 + j];
            }
        }
    }
}

// ---------------- launch ------------------------------------------------------
extern "C" void kernel_launch(void* const* d_in, const int* in_sizes, int n_in,
                              void* d_out, int out_size) {
    const float* x     = (const float*)d_in[0];
    const int*   ei    = (const int*)d_in[1];
    const float* W1    = (const float*)d_in[2];
    const float* asrc1 = (const float*)d_in[3];
    const float* adst1 = (const float*)d_in[4];
    const float* b1    = (const float*)d_in[5];
    const float* W2    = (const float*)d_in[6];
    const float* asrc2 = (const float*)d_in[7];
    const float* adst2 = (const float*)d_in[8];
    const float* b2    = (const float*)d_in[9];
    float* out = (float*)d_out;

    const int E = in_sizes[1] / 2;       // 524288

    int dev = 0, sms = 0, bpm = 0;
    cudaGetDevice(&dev);
    cudaDeviceGetAttribute(&sms, cudaDevAttrMultiProcessorCount, dev);
    cudaOccupancyMaxActiveBlocksPerMultiprocessor(&bpm, fused_kernel, TPB, 0);
    if (bpm < 1) bpm = 1;
    int G = sms * bpm;
    if (G > 2048) G = 2048;

    void* barp = nullptr;
    cudaGetSymbolAddress(&barp, g_barrier);
    cudaMemsetAsync(barp, 0, 2 * sizeof(unsigned), 0);

    fused_kernel<<<G, TPB>>>(x, ei, E, W1, asrc1, adst1, b1,
                             W2, asrc2, adst2, b2, out, G);
}

// round 6
// speedup vs baseline: 1.1550x; 1.1550x over previous
#include <cuda_runtime.h>
#include <math.h>

#define NN    8192
#define INC   512
#define SLOT  192
#define PMASK 0x7FFFFFFF

// ---------------- scratch (device globals) -----------------------------------
__device__ float g_h1[NN * 64];
__device__ float g_als1[NN * 8];
__device__ float g_ald1[NN * 8];
__device__ float g_out1[NN * 64];
__device__ float g_h2[NN * 64];
__device__ float g_als2[NN];
__device__ float g_ald2[NN];
__device__ float g_x2[NN * 64];
__device__ float g_s2[NN * 64];
__device__ float g_tmp2[NN * 64];
__device__ float g_pool[2 * 4096];
__device__ float g_part[128 * 8192];       // per-chunk pool partials
__device__ int   g_cnt[NN];
__device__ __align__(16) int g_slot[NN * SLOT];

// ---------------- helpers ----------------------------------------------------
__device__ __forceinline__ float warpSum(float v) {
    #pragma unroll
    for (int o = 16; o > 0; o >>= 1) v += __shfl_xor_sync(0xffffffffu, v, o);
    return v;
}
__device__ __forceinline__ float warpMax(float v) {
    #pragma unroll
    for (int o = 16; o > 0; o >>= 1) v = fmaxf(v, __shfl_xor_sync(0xffffffffu, v, o));
    return v;
}
__device__ __forceinline__ float lrelu(float v) { return v > 0.f ? v : 0.2f * v; }

__device__ __forceinline__ void fma2(unsigned long long& d, unsigned long long a, unsigned long long b) {
    asm("fma.rn.f32x2 %0, %1, %2, %0;" : "+l"(d) : "l"(a), "l"(b));
}
__device__ __forceinline__ unsigned long long splat2(float a) {
    unsigned long long r;
    asm("mov.b64 %0, {%1, %1};" : "=l"(r) : "f"(a));
    return r;
}

// ---------------- bucket build (fixed slots) ----------------------------------
__global__ void perm_kernel(const int* __restrict__ ei, int E) {
    int i = blockIdx.x * blockDim.x + threadIdx.x;
    int q = E >> 2;
    if (i < q) {
        int4 s4 = __ldg((const int4*)ei + i);
        int4 d4 = __ldg((const int4*)(ei + E) + i);
        int p0 = atomicAdd(&g_cnt[d4.x], 1);
        int p1 = atomicAdd(&g_cnt[d4.y], 1);
        int p2 = atomicAdd(&g_cnt[d4.z], 1);
        int p3 = atomicAdd(&g_cnt[d4.w], 1);
        if (p0 < SLOT) g_slot[d4.x * SLOT + p0] = s4.x;
        if (p1 < SLOT) g_slot[d4.y * SLOT + p1] = s4.y;
        if (p2 < SLOT) g_slot[d4.z * SLOT + p2] = s4.z;
        if (p3 < SLOT) g_slot[d4.w * SLOT + p3] = s4.w;
    } else if (i < q + NN) {
        int n = i - q;
        int p = atomicAdd(&g_cnt[n], 1);
        if (p < SLOT) g_slot[n * SLOT + p] = n | 0x80000000;
    }
}

// ---------------- sgemm1 (Kd=512) + att1 ---------------------------------------
__global__ void sgemm1_att(const float* __restrict__ A, const float* __restrict__ B,
                           const float* __restrict__ asrc, const float* __restrict__ adst,
                           float* __restrict__ C) {
    __shared__ float As[32][68];
    __shared__ float Bs[32][64];
    __shared__ float Cs[64][66];
    int tid = threadIdx.x;
    int row0 = blockIdx.x * 64;
    int ty = tid >> 4, tx = tid & 15;
    unsigned long long acc[4][2] = {};
    for (int k0 = 0; k0 < INC; k0 += 32) {
        #pragma unroll
        for (int i = tid; i < 64 * 32; i += 256) {
            int m = i >> 5, k = i & 31;
            As[k][m] = A[(row0 + m) * INC + k0 + k];
        }
        #pragma unroll
        for (int i = tid; i < 32 * 64; i += 256) {
            int k = i >> 6, n = i & 63;
            Bs[k][n] = B[(k0 + k) * 64 + n];
        }
        __syncthreads();
        #pragma unroll
        for (int k = 0; k < 32; k++) {
            float4 a4 = *(const float4*)&As[k][ty * 4];
            const unsigned long long* bp = (const unsigned long long*)&Bs[k][tx * 4];
            unsigned long long b01 = bp[0], b23 = bp[1];
            unsigned long long s0 = splat2(a4.x), s1 = splat2(a4.y),
                               s2 = splat2(a4.z), s3 = splat2(a4.w);
            fma2(acc[0][0], s0, b01); fma2(acc[0][1], s0, b23);
            fma2(acc[1][0], s1, b01); fma2(acc[1][1], s1, b23);
            fma2(acc[2][0], s2, b01); fma2(acc[2][1], s2, b23);
            fma2(acc[3][0], s3, b01); fma2(acc[3][1], s3, b23);
        }
        __syncthreads();
    }
    #pragma unroll
    for (int i = 0; i < 4; i++) {
        unsigned long long* cp = (unsigned long long*)&C[(row0 + ty * 4 + i) * 64 + tx * 4];
        cp[0] = acc[i][0]; cp[1] = acc[i][1];
        unsigned long long* sp = (unsigned long long*)&Cs[ty * 4 + i][tx * 4];
        sp[0] = acc[i][0]; sp[1] = acc[i][1];
    }
    __syncthreads();
    #pragma unroll
    for (int idx = tid; idx < 512; idx += 256) {
        int n = idx >> 3, h = idx & 7;
        const float* hp = &Cs[n][h * 8];
        float s = 0.f, d = 0.f;
        #pragma unroll
        for (int c = 0; c < 8; c++) {
            s += hp[c] * __ldg(asrc + h * 8 + c);
            d += hp[c] * __ldg(adst + h * 8 + c);
        }
        g_als1[(row0 + n) * 8 + h] = s;
        g_ald1[(row0 + n) * 8 + h] = d;
    }
}

// ---------------- sgemm2 (Kd=64) + att2 ----------------------------------------
__global__ void sgemm2_att(const float* __restrict__ A, const float* __restrict__ B,
                           const float* __restrict__ asrc, const float* __restrict__ adst,
                           float* __restrict__ C) {
    __shared__ float As[32][68];
    __shared__ float Bs[32][64];
    __shared__ float Cs[64][66];
    int tid = threadIdx.x;
    int row0 = blockIdx.x * 64;
    int ty = tid >> 4, tx = tid & 15;
    unsigned long long acc[4][2] = {};
    for (int k0 = 0; k0 < 64; k0 += 32) {
        #pragma unroll
        for (int i = tid; i < 64 * 32; i += 256) {
            int m = i >> 5, k = i & 31;
            As[k][m] = A[(row0 + m) * 64 + k0 + k];
        }
        #pragma unroll
        for (int i = tid; i < 32 * 64; i += 256) {
            int k = i >> 6, n = i & 63;
            Bs[k][n] = B[(k0 + k) * 64 + n];
        }
        __syncthreads();
        #pragma unroll
        for (int k = 0; k < 32; k++) {
            float4 a4 = *(const float4*)&As[k][ty * 4];
            const unsigned long long* bp = (const unsigned long long*)&Bs[k][tx * 4];
            unsigned long long b01 = bp[0], b23 = bp[1];
            unsigned long long s0 = splat2(a4.x), s1 = splat2(a4.y),
                               s2 = splat2(a4.z), s3 = splat2(a4.w);
            fma2(acc[0][0], s0, b01); fma2(acc[0][1], s0, b23);
            fma2(acc[1][0], s1, b01); fma2(acc[1][1], s1, b23);
            fma2(acc[2][0], s2, b01); fma2(acc[2][1], s2, b23);
            fma2(acc[3][0], s3, b01); fma2(acc[3][1], s3, b23);
        }
        __syncthreads();
    }
    #pragma unroll
    for (int i = 0; i < 4; i++) {
        unsigned long long* cp = (unsigned long long*)&C[(row0 + ty * 4 + i) * 64 + tx * 4];
        cp[0] = acc[i][0]; cp[1] = acc[i][1];
        unsigned long long* sp = (unsigned long long*)&Cs[ty * 4 + i][tx * 4];
        sp[0] = acc[i][0]; sp[1] = acc[i][1];
    }
    __syncthreads();
    {
        int n = tid >> 2, q = tid & 3;
        const float* hp = &Cs[n][q * 16];
        float s = 0.f, d = 0.f;
        #pragma unroll
        for (int c = 0; c < 16; c++) {
            float hv = hp[c];
            s += hv * __ldg(asrc + q * 16 + c);
            d += hv * __ldg(adst + q * 16 + c);
        }
        s += __shfl_xor_sync(0xffffffffu, s, 1);
        s += __shfl_xor_sync(0xffffffffu, s, 2);
        d += __shfl_xor_sync(0xffffffffu, d, 1);
        d += __shfl_xor_sync(0xffffffffu, d, 2);
        if (q == 0) { g_als2[row0 + n] = s; g_ald2[row0 + n] = d; }
    }
}

// ---------------- layer-1 gather (unroll-8 pipelined) --------------------------
__global__ void __launch_bounds__(256, 4) gather1_kernel(const float* __restrict__ b1) {
    int node = (blockIdx.x * blockDim.x + threadIdx.x) >> 5;
    if (node >= NN) return;
    int lane = threadIdx.x & 31;
    int c0 = lane * 2;
    int h = lane >> 2;
    int cnt = min(__ldg(g_cnt + node), SLOT);
    int base = node * SLOT;
    float ald = __ldg(g_ald1 + node * 8 + h);
    float a0c = 0.f, a1c = 0.f, den = 0.f;
    int e = 0;
    for (; e + 8 <= cnt; e += 8) {
        int4 A = *(const int4*)(g_slot + base + e);
        int4 B = *(const int4*)(g_slot + base + e + 4);
        int p0 = A.x & PMASK, p1 = A.y & PMASK, p2 = A.z & PMASK, p3 = A.w & PMASK;
        int p4 = B.x & PMASK, p5 = B.y & PMASK, p6 = B.z & PMASK, p7 = B.w & PMASK;
        float s0 = __ldg(g_als1 + p0 * 8 + h);
        float s1 = __ldg(g_als1 + p1 * 8 + h);
        float s2 = __ldg(g_als1 + p2 * 8 + h);
        float s3 = __ldg(g_als1 + p3 * 8 + h);
        float s4 = __ldg(g_als1 + p4 * 8 + h);
        float s5 = __ldg(g_als1 + p5 * 8 + h);
        float s6 = __ldg(g_als1 + p6 * 8 + h);
        float s7 = __ldg(g_als1 + p7 * 8 + h);
        float2 h0 = *(const float2*)(g_h1 + p0 * 64 + c0);
        float2 h1 = *(const float2*)(g_h1 + p1 * 64 + c0);
        float2 h2 = *(const float2*)(g_h1 + p2 * 64 + c0);
        float2 h3 = *(const float2*)(g_h1 + p3 * 64 + c0);
        float2 h4 = *(const float2*)(g_h1 + p4 * 64 + c0);
        float2 h5 = *(const float2*)(g_h1 + p5 * 64 + c0);
        float2 h6 = *(const float2*)(g_h1 + p6 * 64 + c0);
        float2 h7 = *(const float2*)(g_h1 + p7 * 64 + c0);
        float x0 = __expf(lrelu(s0 + ald));
        float x1 = __expf(lrelu(s1 + ald));
        float x2 = __expf(lrelu(s2 + ald));
        float x3 = __expf(lrelu(s3 + ald));
        float x4 = __expf(lrelu(s4 + ald));
        float x5 = __expf(lrelu(s5 + ald));
        float x6 = __expf(lrelu(s6 + ald));
        float x7 = __expf(lrelu(s7 + ald));
        den += ((x0 + x1) + (x2 + x3)) + ((x4 + x5) + (x6 + x7));
        a0c += x0 * h0.x + x1 * h1.x + x2 * h2.x + x3 * h3.x;
        a0c += x4 * h4.x + x5 * h5.x + x6 * h6.x + x7 * h7.x;
        a1c += x0 * h0.y + x1 * h1.y + x2 * h2.y + x3 * h3.y;
        a1c += x4 * h4.y + x5 * h5.y + x6 * h6.y + x7 * h7.y;
    }
    for (; e < cnt; e++) {
        int p = __ldg(g_slot + base + e) & PMASK;
        float xv = __expf(lrelu(__ldg(g_als1 + p * 8 + h) + ald));
        float2 hv = *(const float2*)(g_h1 + p * 64 + c0);
        den += xv;
        a0c += xv * hv.x;
        a1c += xv * hv.y;
    }
    den += 1e-16f;
    float v0 = a0c / den + __ldg(b1 + c0);
    float v1 = a1c / den + __ldg(b1 + c0 + 1);
    float2 o;
    o.x = v0 > 0.f ? v0 : (__expf(v0) - 1.f);
    o.y = v1 > 0.f ? v1 : (__expf(v1) - 1.f);
    *(float2*)(g_out1 + node * 64 + c0) = o;
}

// ---------------- layer-2 gather + bias + double softmax ----------------------
__global__ void __launch_bounds__(256, 4) gather2_kernel(const float* __restrict__ b2,
                                                         float* __restrict__ outS) {
    int node = (blockIdx.x * blockDim.x + threadIdx.x) >> 5;
    if (node >= NN) return;
    int lane = threadIdx.x & 31;
    int c0 = lane * 2;
    int cnt = min(__ldg(g_cnt + node), SLOT);
    int base = node * SLOT;
    float ald = __ldg(g_ald2 + node);
    float a0c = 0.f, a1c = 0.f, den = 0.f;
    int e = 0;
    for (; e + 8 <= cnt; e += 8) {
        int4 A = *(const int4*)(g_slot + base + e);
        int4 B = *(const int4*)(g_slot + base + e + 4);
        int p0 = A.x & PMASK, p1 = A.y & PMASK, p2 = A.z & PMASK, p3 = A.w & PMASK;
        int p4 = B.x & PMASK, p5 = B.y & PMASK, p6 = B.z & PMASK, p7 = B.w & PMASK;
        float s0 = __ldg(g_als2 + p0);
        float s1 = __ldg(g_als2 + p1);
        float s2 = __ldg(g_als2 + p2);
        float s3 = __ldg(g_als2 + p3);
        float s4 = __ldg(g_als2 + p4);
        float s5 = __ldg(g_als2 + p5);
        float s6 = __ldg(g_als2 + p6);
        float s7 = __ldg(g_als2 + p7);
        float2 h0 = *(const float2*)(g_h2 + p0 * 64 + c0);
        float2 h1 = *(const float2*)(g_h2 + p1 * 64 + c0);
        float2 h2v = *(const float2*)(g_h2 + p2 * 64 + c0);
        float2 h3 = *(const float2*)(g_h2 + p3 * 64 + c0);
        float2 h4 = *(const float2*)(g_h2 + p4 * 64 + c0);
        float2 h5 = *(const float2*)(g_h2 + p5 * 64 + c0);
        float2 h6 = *(const float2*)(g_h2 + p6 * 64 + c0);
        float2 h7 = *(const float2*)(g_h2 + p7 * 64 + c0);
        float x0 = __expf(lrelu(s0 + ald));
        float x1 = __expf(lrelu(s1 + ald));
        float x2 = __expf(lrelu(s2 + ald));
        float x3 = __expf(lrelu(s3 + ald));
        float x4 = __expf(lrelu(s4 + ald));
        float x5 = __expf(lrelu(s5 + ald));
        float x6 = __expf(lrelu(s6 + ald));
        float x7 = __expf(lrelu(s7 + ald));
        den += ((x0 + x1) + (x2 + x3)) + ((x4 + x5) + (x6 + x7));
        a0c += x0 * h0.x + x1 * h1.x + x2 * h2v.x + x3 * h3.x;
        a0c += x4 * h4.x + x5 * h5.x + x6 * h6.x + x7 * h7.x;
        a1c += x0 * h0.y + x1 * h1.y + x2 * h2v.y + x3 * h3.y;
        a1c += x4 * h4.y + x5 * h5.y + x6 * h6.y + x7 * h7.y;
    }
    for (; e < cnt; e++) {
        int p = __ldg(g_slot + base + e) & PMASK;
        float xv = __expf(lrelu(__ldg(g_als2 + p) + ald));
        float2 hv = *(const float2*)(g_h2 + p * 64 + c0);
        den += xv;
        a0c += xv * hv.x;
        a1c += xv * hv.y;
    }
    den += 1e-16f;
    float v0 = a0c / den + __ldg(b2 + c0);
    float v1 = a1c / den + __ldg(b2 + c0 + 1);
    *(float2*)(g_x2 + node * 64 + c0) = make_float2(v0, v1);
    float m = warpMax(fmaxf(v0, v1));
    float e0 = __expf(v0 - m), e1 = __expf(v1 - m);
    float sum = warpSum(e0 + e1);
    float s0v = e0 / sum, s1v = e1 / sum;
    *(float2*)(outS + node * 64 + c0) = make_float2(s0v, s1v);
    float m2 = warpMax(fmaxf(s0v, s1v));
    float f0 = __expf(s0v - m2), f1 = __expf(s1v - m2);
    float sum2 = warpSum(f0 + f1);
    *(float2*)(g_s2 + node * 64 + c0) = make_float2(f0 / sum2, f1 / sum2);
}

// ---------------- adjacency gather -------------------------------------------
__global__ void __launch_bounds__(256, 4) adj_gather_kernel() {
    int node = (blockIdx.x * blockDim.x + threadIdx.x) >> 5;
    if (node >= NN) return;
    int lane = threadIdx.x & 31;
    int c0 = lane * 2;
    int cnt = min(__ldg(g_cnt + node), SLOT);
    int base = node * SLOT;
    float a0c = 0.f, a1c = 0.f;
    int e = 0;
    for (; e + 8 <= cnt; e += 8) {
        int4 A = *(const int4*)(g_slot + base + e);
        int4 B = *(const int4*)(g_slot + base + e + 4);
        float2 s0 = *(const float2*)(g_s2 + (A.x & PMASK) * 64 + c0);
        float2 s1 = *(const float2*)(g_s2 + (A.y & PMASK) * 64 + c0);
        float2 s2v = *(const float2*)(g_s2 + (A.z & PMASK) * 64 + c0);
        float2 s3 = *(const float2*)(g_s2 + (A.w & PMASK) * 64 + c0);
        float2 s4 = *(const float2*)(g_s2 + (B.x & PMASK) * 64 + c0);
        float2 s5 = *(const float2*)(g_s2 + (B.y & PMASK) * 64 + c0);
        float2 s6 = *(const float2*)(g_s2 + (B.z & PMASK) * 64 + c0);
        float2 s7 = *(const float2*)(g_s2 + (B.w & PMASK) * 64 + c0);
        if (A.x >= 0) { a0c += s0.x;  a1c += s0.y; }
        if (A.y >= 0) { a0c += s1.x;  a1c += s1.y; }
        if (A.z >= 0) { a0c += s2v.x; a1c += s2v.y; }
        if (A.w >= 0) { a0c += s3.x;  a1c += s3.y; }
        if (B.x >= 0) { a0c += s4.x;  a1c += s4.y; }
        if (B.y >= 0) { a0c += s5.x;  a1c += s5.y; }
        if (B.z >= 0) { a0c += s6.x;  a1c += s6.y; }
        if (B.w >= 0) { a0c += s7.x;  a1c += s7.y; }
    }
    for (; e < cnt; e++) {
        int p = __ldg(g_slot + base + e);
        if (p < 0) continue;
        float2 sv = *(const float2*)(g_s2 + p * 64 + c0);
        a0c += sv.x;
        a1c += sv.y;
    }
    *(float2*)(g_tmp2 + node * 64 + c0) = make_float2(a0c, a1c);
}

// ---------------- pool partials (no atomics) -----------------------------------
__global__ void pool_part() {
    int i = threadIdx.x >> 2;
    int jb = (threadIdx.x & 3) * 16;
    int chunk = blockIdx.x;                 // 128 chunks of 64 nodes
    int base = chunk * 64;
    float accA[16] = {}, accX[16] = {};
    for (int n = 0; n < 64; n++) {
        int node = base + n;
        float ti = __ldg(g_tmp2 + node * 64 + i);
        float si = __ldg(g_s2 + node * 64 + i);
        const float4* s4 = (const float4*)(g_s2 + node * 64 + jb);
        const float4* x4 = (const float4*)(g_x2 + node * 64 + jb);
        #pragma unroll
        for (int q = 0; q < 4; q++) {
            float4 sv = __ldg(s4 + q), xv = __ldg(x4 + q);
            accA[q * 4 + 0] += ti * sv.x; accA[q * 4 + 1] += ti * sv.y;
            accA[q * 4 + 2] += ti * sv.z; accA[q * 4 + 3] += ti * sv.w;
            accX[q * 4 + 0] += si * xv.x; accX[q * 4 + 1] += si * xv.y;
            accX[q * 4 + 2] += si * xv.z; accX[q * 4 + 3] += si * xv.w;
        }
    }
    float* pa = g_part + chunk * 8192;
    #pragma unroll
    for (int u = 0; u < 16; u++) {
        pa[i * 64 + jb + u] = accA[u];
        pa[4096 + i * 64 + jb + u] = accX[u];
    }
}

// ---------------- reduce partials ----------------------------------------------
__global__ void reduceP() {
    int idx = blockIdx.x * blockDim.x + threadIdx.x;   // 8192 outputs
    if (idx >= 8192) return;
    float s = 0.f;
    #pragma unroll 8
    for (int b = 0; b < 128; b++) s += g_part[b * 8192 + idx];
    g_pool[idx] = s;
}

// ---------------- finalize ----------------------------------------------------
__global__ void finalize(float* __restrict__ out) {
    __shared__ float sd[64];
    int i = threadIdx.x;
    float rs = 0.f;
    for (int j = 0; j < 64; j++) {
        float v = (j == i) ? 0.f : g_pool[i * 64 + j];
        rs += v;
    }
    sd[i] = sqrtf(rs) + 1e-15f;
    __syncthreads();
    for (int j = 0; j < 64; j++) {
        float v = (j == i) ? 0.f : g_pool[i * 64 + j];
        out[4096 + i * 64 + j] = v / sd[j] / sd[i];
        out[i * 64 + j] = g_pool[4096 + i * 64 + j];
    }
}

// ---------------- launch ------------------------------------------------------
extern "C" void kernel_launch(void* const* d_in, const int* in_sizes, int n_in,
                              void* d_out, int out_size) {
    const float* x     = (const float*)d_in[0];
    const int*   ei    = (const int*)d_in[1];
    const float* W1    = (const float*)d_in[2];
    const float* asrc1 = (const float*)d_in[3];
    const float* adst1 = (const float*)d_in[4];
    const float* b1    = (const float*)d_in[5];
    const float* W2    = (const float*)d_in[6];
    const float* asrc2 = (const float*)d_in[7];
    const float* adst2 = (const float*)d_in[8];
    const float* b2    = (const float*)d_in[9];
    float* out = (float*)d_out;

    const int E = in_sizes[1] / 2;       // 524288
    const int q4 = (E >> 2) + NN;

    static bool inited = false;
    static cudaStream_t sB;
    static cudaEvent_t evA, evB;
    if (!inited) {
        cudaStreamCreateWithFlags(&sB, cudaStreamNonBlocking);
        cudaEventCreateWithFlags(&evA, cudaEventDisableTiming);
        cudaEventCreateWithFlags(&evB, cudaEventDisableTiming);
        inited = true;
    }

    float *h1p, *out1p, *h2p;
    int *cntp;
    cudaGetSymbolAddress((void**)&h1p, g_h1);
    cudaGetSymbolAddress((void**)&out1p, g_out1);
    cudaGetSymbolAddress((void**)&h2p, g_h2);
    cudaGetSymbolAddress((void**)&cntp, g_cnt);

    cudaMemsetAsync(cntp, 0, NN * sizeof(int), 0);

    // fork: bucket build ∥ sgemm1
    cudaEventRecord(evA, 0);
    cudaStreamWaitEvent(sB, evA, 0);
    perm_kernel<<<(q4 + 255) / 256, 256, 0, sB>>>(ei, E);
    cudaEventRecord(evB, sB);

    sgemm1_att<<<NN / 64, 256>>>(x, W1, asrc1, adst1, h1p);

    cudaStreamWaitEvent(0, evB, 0);
    gather1_kernel<<<NN * 32 / 256, 256>>>(b1);

    sgemm2_att<<<NN / 64, 256>>>(out1p, W2, asrc2, adst2, h2p);
    gather2_kernel<<<NN * 32 / 256, 256>>>(b2, out + 2 * 4096);

    adj_gather_kernel<<<NN * 32 / 256, 256>>>();
    pool_part<<<128, 256>>>();
    reduceP<<<32, 256>>>();
    finalize<<<1, 64>>>(out);
}